// round 11
// baseline (speedup 1.0000x reference)
#include <cuda_runtime.h>
#include <cuda_bf16.h>

// Chainless persistent WKV scan.
//
// Grid = 512 blocks (one per 32-channel group), all co-resident at 4/SM.
// Each block loops over the 16 chunks of 128 timesteps, carrying the scan
// state (a0,b0) per channel in double-buffered smem. No flags, no global
// prefixes, no inter-block sync of any kind.
//
// Per chunk (identical to R9): 256 threads = 32 channels x 8 sub-segments
// of 16 steps. Thread-local normalized scan (decay product cancels in b/a):
//   cw_i = sum w ; e_i = exp(k_i - cw_i) ; ah_i = sum e ; bh_i = sum e*v
// Sub-segment affine map: a_out = P*a_in + P*aa, P = exp(cw_end).
// Warp 0 composes the 8 maps -> exclusive prefixes (linear in a0) + new carry.

#define BATCH  16
#define TLEN   2048
#define DIM    1024
#define CHAN   (BATCH * DIM)       // 16384
#define NCH    32                  // channels per block
#define NSUB   8                   // sub-segments per chunk
#define SUBSEG 16                  // timesteps per thread per chunk
#define SEGT   (NSUB * SUBSEG)     // 128 timesteps per chunk
#define NSEG   (TLEN / SEGT)       // 16 chunks
#define NCG    (CHAN / NCH)        // 512 blocks
#define BLKT   (NCH * NSUB)        // 256 threads

__global__ __launch_bounds__(BLKT, 4)
void wkv_persist(const float* __restrict__ K,
                 const float* __restrict__ V,
                 const float* __restrict__ W,
                 float* __restrict__ O) {
    const int cg   = blockIdx.x;
    const int tid  = threadIdx.x;
    const int lane = tid & (NCH - 1);       // channel within group
    const int sub  = tid >> 5;              // sub-segment 0..7
    const int c    = cg * NCH + lane;       // global channel
    const int b    = c >> 10;               // / DIM
    const int d    = c & (DIM - 1);         // % DIM

    __shared__ float sP [NSUB][NCH], sQa[NSUB][NCH], sQb[NSUB][NCH];
    __shared__ float sBt[NSUB][NCH], sAl[NSUB][NCH], sBl[NSUB][NCH];
    __shared__ float sA0[2][NCH], sB0[2][NCH];   // double-buffered carry

    if (tid < NCH) { sA0[0][tid] = 0.0f; sB0[0][tid] = 0.0f; }

    size_t base = (size_t)b * TLEN * DIM + (size_t)(sub * SUBSEG) * DIM + d;
    const float* kp = K + base;
    const float* vp = V + base;
    const float* wp = W + base;
    float*       op = O + base;

    int p = 0;
    for (int s = 0; s < NSEG; ++s) {
        // ---- front-batched streaming loads (48 LDG.CS) ----
        float wb[SUBSEG], kb[SUBSEG], vb[SUBSEG];
#pragma unroll
        for (int i = 0; i < SUBSEG; ++i) wb[i] = __ldcs(wp + i * DIM);
#pragma unroll
        for (int i = 0; i < SUBSEG; ++i) kb[i] = __ldcs(kp + i * DIM);
#pragma unroll
        for (int i = 0; i < SUBSEG; ++i) vb[i] = __ldcs(vp + i * DIM);

        // ---- normalized local scan; reuse kb -> ah, vb -> bh ----
        float cw = 0.0f, aa = 0.0f, bb = 0.0f;
#pragma unroll
        for (int i = 0; i < SUBSEG; ++i) {
            cw += wb[i];
            const float e = __expf(kb[i] - cw);
            aa += e;
            bb = fmaf(e, vb[i], bb);
            kb[i] = aa;      // ah
            vb[i] = bb;      // bh
        }
        const float P = __expf(cw);
        sP [sub][lane] = P;
        sQa[sub][lane] = P * aa;
        sQb[sub][lane] = P * bb;
        __syncthreads();

        // ---- warp 0: compose 8 maps per channel, advance carry ----
        if (tid < NCH) {
            float beta = 1.0f, alA = 0.0f, alB = 0.0f;
#pragma unroll
            for (int j = 0; j < NSUB; ++j) {
                sBt[j][tid] = beta;
                sAl[j][tid] = alA;
                sBl[j][tid] = alB;
                const float pj = sP[j][tid];
                beta = pj * beta;
                alA  = fmaf(pj, alA, sQa[j][tid]);
                alB  = fmaf(pj, alB, sQb[j][tid]);
            }
            const float a0 = sA0[p][tid];
            const float b0 = sB0[p][tid];
            sA0[p ^ 1][tid] = fmaf(beta, a0, alA);
            sB0[p ^ 1][tid] = fmaf(beta, b0, alB);
        }
        __syncthreads();

        // ---- outputs (streaming stores) ----
        const float beta = sBt[sub][lane];
        const float A_in = fmaf(beta, sA0[p][lane], sAl[sub][lane]);
        const float B_in = fmaf(beta, sB0[p][lane], sBl[sub][lane]);
#pragma unroll
        for (int i = 0; i < SUBSEG; ++i)
            __stcs(op + i * DIM, __fdividef(B_in + vb[i], A_in + kb[i]));

        p ^= 1;
        kp += SEGT * DIM; vp += SEGT * DIM; wp += SEGT * DIM; op += SEGT * DIM;
    }
}

extern "C" void kernel_launch(void* const* d_in, const int* in_sizes, int n_in,
                              void* d_out, int out_size) {
    const float* K = (const float*)d_in[0];
    const float* V = (const float*)d_in[1];
    const float* W = (const float*)d_in[2];
    float*       O = (float*)d_out;

    wkv_persist<<<NCG, BLKT>>>(K, V, W, O);   // 512 blocks, all co-resident
}